// round 10
// baseline (speedup 1.0000x reference)
#include <cuda_runtime.h>
#include <math.h>

// Problem constants: B=16, C=512, H=W=64, G=16, CPG=32, HID=8
#define BN   16
#define CN   512
#define GN   16
#define CPGN 32
#define HIDN 8
#define HWN  4096   // 64*64
#define NIMG (BN * CN)

__device__ float g_pooled[NIMG];
__device__ float g_scale[NIMG];
// Monotonic across graph replays — never reset.
// g_batch_cnt: (count & 511)==511 marks the last pool block of a batch.
// g_ready:     per-batch epoch; bumped once per replay when gates are done.
__device__ unsigned g_batch_cnt[BN];
__device__ volatile unsigned g_ready[BN];

__device__ __forceinline__ float sigmoidf_(float v) {
    return 1.0f / (1.0f + expf(-v));
}

// ---------------------------------------------------------------------------
// Single kernel: pool -> (last block of batch: gate math, bump epoch) ->
// spin on epoch -> scale own image. Stream-K-style forward-progress chain:
// block bc only waits on blocks with indices in the same 512-block batch,
// which are dispatched before/with it (monotonic CTA dispatch), and one full
// batch (512 CTAs) is far below residency (~1184 CTAs).
// ---------------------------------------------------------------------------
__global__ void __launch_bounds__(256)
fused_kernel(const float* __restrict__ x, float* __restrict__ out,
             const float* __restrict__ gw1, const float* __restrict__ gb1,
             const float* __restrict__ gw2, const float* __restrict__ gb2,
             const float* __restrict__ cw1, const float* __restrict__ cb1,
             const float* __restrict__ cw2, const float* __restrict__ cb2) {
    const int bc = blockIdx.x;            // image index == output image index
    const int tid = threadIdx.x;
    const int b = bc >> 9;

    __shared__ unsigned epoch0;
    __shared__ bool is_last;

    // Capture the batch epoch BEFORE this block's pool contribution: the
    // epoch for this replay cannot have been bumped yet (it requires our
    // pool), so epoch0 is always the pre-bump value. Replay-safe.
    if (tid == 0) epoch0 = g_ready[b];

    // ---- pooling for this block's image ----
    {
        const float4* p = reinterpret_cast<const float4*>(x + (size_t)bc * HWN);
        float4 v[4];
#pragma unroll
        for (int i = 0; i < 4; i++) v[i] = p[tid + i * 256];
        float s = 0.f;
#pragma unroll
        for (int i = 0; i < 4; i++) s += (v[i].x + v[i].y) + (v[i].z + v[i].w);
#pragma unroll
        for (int o = 16; o; o >>= 1) s += __shfl_down_sync(0xffffffffu, s, o);
        __shared__ float ws[8];
        if ((tid & 31) == 0) ws[tid >> 5] = s;
        __syncthreads();
        if (tid == 0) {
            float t = 0.f;
#pragma unroll
            for (int i = 0; i < 8; i++) t += ws[i];
            g_pooled[bc] = t * (1.0f / HWN);
        }
    }

    __threadfence();                      // publish g_pooled[bc]
    __syncthreads();
    if (tid == 0) is_last = ((atomicAdd(&g_batch_cnt[b], 1u) & (CN - 1)) == CN - 1);
    __syncthreads();

    // ---- last pool block of this batch runs the full gate math ----
    if (is_last) {
        __shared__ float pooled1[CN], gate1[CN], pooled2[CN], gate2[CN];
        __shared__ float h[GN][HIDN];
        __shared__ float glob[GN], wv[GN], hc[HIDN];

#pragma unroll
        for (int ch = tid; ch < CN; ch += 256) pooled1[ch] = __ldcg(&g_pooled[b * CN + ch]);
        __syncthreads();

        // SE pass 1 hidden: 16 groups x 8 hid = 128 lanes
        if (tid < GN * HIDN) {
            const int g = tid >> 3, c = tid & 7;
            float s = gb1[c];
#pragma unroll
            for (int j = 0; j < CPGN; j++) s += pooled1[g * CPGN + j] * gw1[c * CPGN + j];
            h[g][c] = fmaxf(s, 0.f);
        }
        __syncthreads();
#pragma unroll
        for (int ch = tid; ch < CN; ch += 256) {
            const int g = ch >> 5, c = ch & 31;
            float s = gb2[c];
#pragma unroll
            for (int o = 0; o < HIDN; o++) s += h[g][o] * gw2[c * HIDN + o];
            gate1[ch] = sigmoidf_(s);
        }
        __syncthreads();

        // channel shuffle on pooled values: ch2 -> ch_orig
#pragma unroll
        for (int ch = tid; ch < CN; ch += 256) {
            const int g1 = ch & 15, cpg1 = ch >> 4;
            const int och = g1 * CPGN + cpg1;
            pooled2[ch] = pooled1[och] * gate1[och];
        }
        __syncthreads();

        // SE pass 2
        if (tid < GN * HIDN) {
            const int g = tid >> 3, c = tid & 7;
            float s = gb1[c];
#pragma unroll
            for (int j = 0; j < CPGN; j++) s += pooled2[g * CPGN + j] * gw1[c * CPGN + j];
            h[g][c] = fmaxf(s, 0.f);
        }
        __syncthreads();
#pragma unroll
        for (int ch = tid; ch < CN; ch += 256) {
            const int g = ch >> 5, c = ch & 31;
            float s = gb2[c];
#pragma unroll
            for (int o = 0; o < HIDN; o++) s += h[g][o] * gw2[c * HIDN + o];
            gate2[ch] = sigmoidf_(s);
        }
        __syncthreads();

        // cross-group gate
        if (tid < GN) {
            float s = 0.f;
#pragma unroll
            for (int j = 0; j < CPGN; j++) s += pooled2[tid * CPGN + j] * gate2[tid * CPGN + j];
            glob[tid] = s * (1.0f / CPGN);
        }
        __syncthreads();
        if (tid < HIDN) {
            float s = cb1[tid];
#pragma unroll
            for (int j = 0; j < GN; j++) s += glob[j] * cw1[tid * GN + j];
            hc[tid] = fmaxf(s, 0.f);
        }
        __syncthreads();
        if (tid < GN) {
            float s = cb2[tid];
#pragma unroll
            for (int o = 0; o < HIDN; o++) s += hc[o] * cw2[tid * HIDN + o];
            wv[tid] = sigmoidf_(s);
        }
        __syncthreads();

        // compose final per-channel scale, indexed by output channel
#pragma unroll
        for (int ch = tid; ch < CN; ch += 256) {       // ch == ch2
            const int g2 = ch >> 5, c2 = ch & 31;
            const int g1 = ch & 15, cpg1 = ch >> 4;
            const int och = g1 * CPGN + cpg1;
            const float s = gate1[och] * gate2[ch] * wv[g2];
            const int ch_out = c2 * GN + g2;
            g_scale[b * CN + ch_out] = s;
        }
        __threadfence();                  // publish g_scale before epoch bump
        __syncthreads();
        if (tid == 0) atomicAdd((unsigned*)&g_ready[b], 1u);
    }

    // ---- wait for this batch's gates, then scale own image ----
    if (tid == 0) {
        while (g_ready[b] == epoch0) __nanosleep(64);
    }
    __syncthreads();
    __threadfence();                      // acquire

    {
        const int ch_out = bc & 511;
        const int c2 = ch_out >> 4, g2 = ch_out & 15;
        const int ch2 = g2 * CPGN + c2;
        const int g1 = ch2 & 15, cpg1 = ch2 >> 4;
        const int och = g1 * CPGN + cpg1;

        const float s = __ldcg(&g_scale[bc]);
        const float4* pin  = reinterpret_cast<const float4*>(x + ((size_t)b * CN + och) * HWN);
        float4* pout = reinterpret_cast<float4*>(out + (size_t)bc * HWN);

        float4 v[4];
#pragma unroll
        for (int i = 0; i < 4; i++) v[i] = pin[tid + i * 256];
#pragma unroll
        for (int i = 0; i < 4; i++) {
            v[i].x *= s; v[i].y *= s; v[i].z *= s; v[i].w *= s;
            __stcs(&pout[tid + i * 256], v[i]);
        }
    }
}

extern "C" void kernel_launch(void* const* d_in, const int* in_sizes, int n_in,
                              void* d_out, int out_size) {
    const float* x   = (const float*)d_in[0];
    const float* gw1 = (const float*)d_in[1];
    const float* gb1 = (const float*)d_in[2];
    const float* gw2 = (const float*)d_in[3];
    const float* gb2 = (const float*)d_in[4];
    const float* cw1 = (const float*)d_in[5];
    const float* cb1 = (const float*)d_in[6];
    const float* cw2 = (const float*)d_in[7];
    const float* cb2 = (const float*)d_in[8];
    float* out = (float*)d_out;

    fused_kernel<<<NIMG, 256>>>(x, out, gw1, gb1, gw2, gb2, cw1, cb1, cw2, cb2);
}

// round 11
// speedup vs baseline: 1.7899x; 1.7899x over previous
#include <cuda_runtime.h>
#include <math.h>

// Problem constants: B=16, C=512, H=W=64, G=16, CPG=32, HID=8
#define BN   16
#define CN   512
#define GN   16
#define CPGN 32
#define HIDN 8
#define HWN  4096   // 64*64
#define NIMG (BN * CN)

__device__ float g_pooled[NIMG];
__device__ float g_scale[NIMG];
// Zero-initialized at module load, NEVER reset: monotonic counter.
// (count & 511) == 511 marks the last pool block of a batch on every graph
// replay because 512 divides 2^32. Validated in R9/R10.
__device__ unsigned g_batch_cnt[BN];

__device__ __forceinline__ float sigmoidf_(float v) {
    return 1.0f / (1.0f + expf(-v));
}

// ---------------------------------------------------------------------------
// Kernel 1: spatial mean per (b,c); the last pool block of each batch then
// runs the full gate math for that batch. Ascending image order leaves the
// x tail L2-resident for the scale kernel.
// ---------------------------------------------------------------------------
__global__ void __launch_bounds__(256)
pool_gate_kernel(const float* __restrict__ x,
                 const float* __restrict__ gw1, const float* __restrict__ gb1,
                 const float* __restrict__ gw2, const float* __restrict__ gb2,
                 const float* __restrict__ cw1, const float* __restrict__ cb1,
                 const float* __restrict__ cw2, const float* __restrict__ cb2) {
    const int bc = blockIdx.x;  // 0 .. 8191
    const int tid = threadIdx.x;
    const int b = bc >> 9;

    // ---- pooling for this block's image ----
    {
        const float4* p = reinterpret_cast<const float4*>(x + (size_t)bc * HWN);
        float4 v[4];
#pragma unroll
        for (int i = 0; i < 4; i++) v[i] = p[tid + i * 256];
        float s = 0.f;
#pragma unroll
        for (int i = 0; i < 4; i++) s += (v[i].x + v[i].y) + (v[i].z + v[i].w);
#pragma unroll
        for (int o = 16; o; o >>= 1) s += __shfl_down_sync(0xffffffffu, s, o);
        __shared__ float ws[8];
        if ((tid & 31) == 0) ws[tid >> 5] = s;
        __syncthreads();
        if (tid == 0) {
            float t = 0.f;
#pragma unroll
            for (int i = 0; i < 8; i++) t += ws[i];
            g_pooled[bc] = t * (1.0f / HWN);
        }
    }

    // ---- last pool block of this batch runs the gate math ----
    __shared__ bool is_last;
    __threadfence();                     // publish g_pooled[bc]
    __syncthreads();
    if (tid == 0) is_last = ((atomicAdd(&g_batch_cnt[b], 1u) & (CN - 1)) == CN - 1);
    __syncthreads();
    if (!is_last) return;
    __threadfence();                     // see all other blocks' g_pooled

    __shared__ float pooled1[CN], gate1[CN], pooled2[CN], gate2[CN];
    __shared__ float h[GN][HIDN];
    __shared__ float glob[GN], wv[GN], hc[HIDN];

#pragma unroll
    for (int ch = tid; ch < CN; ch += 256) pooled1[ch] = __ldcg(&g_pooled[b * CN + ch]);
    __syncthreads();

    // SE pass 1 hidden: 16 groups x 8 hid = 128 lanes
    if (tid < GN * HIDN) {
        const int g = tid >> 3, c = tid & 7;
        float s = gb1[c];
#pragma unroll
        for (int j = 0; j < CPGN; j++) s += pooled1[g * CPGN + j] * gw1[c * CPGN + j];
        h[g][c] = fmaxf(s, 0.f);
    }
    __syncthreads();
#pragma unroll
    for (int ch = tid; ch < CN; ch += 256) {
        const int g = ch >> 5, c = ch & 31;
        float s = gb2[c];
#pragma unroll
        for (int o = 0; o < HIDN; o++) s += h[g][o] * gw2[c * HIDN + o];
        gate1[ch] = sigmoidf_(s);
    }
    __syncthreads();

    // channel shuffle on pooled values: ch2 -> ch_orig
#pragma unroll
    for (int ch = tid; ch < CN; ch += 256) {
        const int g1 = ch & 15, cpg1 = ch >> 4;
        const int och = g1 * CPGN + cpg1;
        pooled2[ch] = pooled1[och] * gate1[och];
    }
    __syncthreads();

    // SE pass 2
    if (tid < GN * HIDN) {
        const int g = tid >> 3, c = tid & 7;
        float s = gb1[c];
#pragma unroll
        for (int j = 0; j < CPGN; j++) s += pooled2[g * CPGN + j] * gw1[c * CPGN + j];
        h[g][c] = fmaxf(s, 0.f);
    }
    __syncthreads();
#pragma unroll
    for (int ch = tid; ch < CN; ch += 256) {
        const int g = ch >> 5, c = ch & 31;
        float s = gb2[c];
#pragma unroll
        for (int o = 0; o < HIDN; o++) s += h[g][o] * gw2[c * HIDN + o];
        gate2[ch] = sigmoidf_(s);
    }
    __syncthreads();

    // cross-group gate
    if (tid < GN) {
        float s = 0.f;
#pragma unroll
        for (int j = 0; j < CPGN; j++) s += pooled2[tid * CPGN + j] * gate2[tid * CPGN + j];
        glob[tid] = s * (1.0f / CPGN);
    }
    __syncthreads();
    if (tid < HIDN) {
        float s = cb1[tid];
#pragma unroll
        for (int j = 0; j < GN; j++) s += glob[j] * cw1[tid * GN + j];
        hc[tid] = fmaxf(s, 0.f);
    }
    __syncthreads();
    if (tid < GN) {
        float s = cb2[tid];
#pragma unroll
        for (int o = 0; o < HIDN; o++) s += hc[o] * cw2[tid * HIDN + o];
        wv[tid] = sigmoidf_(s);
    }
    __syncthreads();

    // compose final per-channel scale, indexed by output channel
#pragma unroll
    for (int ch = tid; ch < CN; ch += 256) {           // ch == ch2
        const int g2 = ch >> 5, c2 = ch & 31;
        const int g1 = ch & 15, cpg1 = ch >> 4;
        const int och = g1 * CPGN + cpg1;
        const float s = gate1[och] * gate2[ch] * wv[g2];
        const int ch_out = c2 * GN + g2;
        g_scale[b * CN + ch_out] = s;
    }
}

// ---------------------------------------------------------------------------
// Kernel 2: out[b, ch_out] = x[b, ch_orig] * scale[b, ch_out].
// Descending image order consumes the L2-resident x tail first; __stcs
// (evict-first) stores keep the write stream from evicting x lines.
// ---------------------------------------------------------------------------
__global__ void __launch_bounds__(256)
scale_kernel(const float* __restrict__ x, float* __restrict__ out) {
    const int bc = NIMG - 1 - blockIdx.x;  // b*512 + ch_out, descending
    const int b = bc >> 9;
    const int ch_out = bc & 511;
    const int c2 = ch_out >> 4, g2 = ch_out & 15;
    const int ch2 = g2 * CPGN + c2;
    const int g1 = ch2 & 15, cpg1 = ch2 >> 4;
    const int och = g1 * CPGN + cpg1;

    const float s = g_scale[bc];
    const float4* pin  = reinterpret_cast<const float4*>(x + ((size_t)b * CN + och) * HWN);
    float4* pout = reinterpret_cast<float4*>(out + (size_t)bc * HWN);

    float4 v[4];
#pragma unroll
    for (int i = 0; i < 4; i++) v[i] = pin[threadIdx.x + i * 256];
#pragma unroll
    for (int i = 0; i < 4; i++) {
        v[i].x *= s; v[i].y *= s; v[i].z *= s; v[i].w *= s;
        __stcs(&pout[threadIdx.x + i * 256], v[i]);
    }
}

extern "C" void kernel_launch(void* const* d_in, const int* in_sizes, int n_in,
                              void* d_out, int out_size) {
    const float* x   = (const float*)d_in[0];
    const float* gw1 = (const float*)d_in[1];
    const float* gb1 = (const float*)d_in[2];
    const float* gw2 = (const float*)d_in[3];
    const float* gb2 = (const float*)d_in[4];
    const float* cw1 = (const float*)d_in[5];
    const float* cb1 = (const float*)d_in[6];
    const float* cw2 = (const float*)d_in[7];
    const float* cb2 = (const float*)d_in[8];
    float* out = (float*)d_out;

    pool_gate_kernel<<<NIMG, 256>>>(x, gw1, gb1, gw2, gb2, cw1, cb1, cw2, cb2);
    scale_kernel<<<NIMG, 256>>>(x, out);
}